// round 2
// baseline (speedup 1.0000x reference)
#include <cuda_runtime.h>
#include <math.h>

// Scratch for the base-module output f: [8192][32][9][9]
static __device__ float g_f_scratch[8192 * 2592];

// ---------------------------------------------------------------------------
// Kernel A: base module. One CTA per sample.
//   conv 3->8 5x5 pad1 + relu -> pool2 -> conv 8->16 3x3 pad1 + relu -> pool2
//   -> conv 16->32 1x1 pad1  => f [32][9][9] written to g_f_scratch
// smem regions (floats): R1 = 3480 (padded x / padded p1 + w_b2 / p2 + w_b3),
//                        R2 = 7200 (c1 / c2), R3 = 608 (w_b1 + b_b1)
// ---------------------------------------------------------------------------
__global__ __launch_bounds__(256) void base_kernel(
    const float* __restrict__ x,
    const float* __restrict__ w_b1, const float* __restrict__ b_b1,
    const float* __restrict__ w_b2, const float* __restrict__ b_b2,
    const float* __restrict__ w_b3, const float* __restrict__ b_b3,
    float* __restrict__ g_f)
{
    __shared__ float sm[3480 + 7200 + 608];
    float* R1 = sm;
    float* R2 = sm + 3480;
    float* R3 = sm + 3480 + 7200;
    const int tid = threadIdx.x;
    const int b = blockIdx.x;
    const float* xb = x + (size_t)b * 3072;

    // Phase 0: zero-pad input to [3][34][34], load w_b1(600)+b_b1(8)
    for (int i = tid; i < 3468; i += 256) R1[i] = 0.f;
    for (int i = tid; i < 608; i += 256) R3[i] = (i < 600) ? w_b1[i] : b_b1[i - 600];
    __syncthreads();
    for (int i = tid; i < 3072; i += 256) {
        int ic = i >> 10, r = i & 1023, iy = r >> 5, ix = r & 31;
        R1[ic * 1156 + (iy + 1) * 34 + (ix + 1)] = xb[i];
    }
    __syncthreads();

    // Phase 1: conv1 (5x5, pad1) + relu -> c1 [8][30][30] in R2
    // Work items: oc(8) x oy(30) x 4-wide x tiles(8) = 1920
    for (int it = tid; it < 1920; it += 256) {
        int oc = it / 240;
        int r = it % 240;
        int oy = r >> 3;
        int ox0 = (r & 7) * 4;
        float bias = R3[600 + oc];
        float acc0 = bias, acc1 = bias, acc2 = bias, acc3 = bias;
        const float* wb = R3 + oc * 75;
        for (int ic = 0; ic < 3; ic++) {
            const float* xrow = R1 + ic * 1156 + oy * 34 + ox0;
            const float* wr = wb + ic * 25;
            #pragma unroll
            for (int ky = 0; ky < 5; ky++) {
                float xr[8];
                #pragma unroll
                for (int j = 0; j < 8; j++)
                    xr[j] = (ox0 + j < 34) ? xrow[ky * 34 + j] : 0.f;
                #pragma unroll
                for (int kx = 0; kx < 5; kx++) {
                    float wv = wr[ky * 5 + kx];
                    acc0 += wv * xr[kx + 0];
                    acc1 += wv * xr[kx + 1];
                    acc2 += wv * xr[kx + 2];
                    acc3 += wv * xr[kx + 3];
                }
            }
        }
        float* crow = R2 + oc * 900 + oy * 30 + ox0;
        if (ox0 + 0 < 30) crow[0] = fmaxf(acc0, 0.f);
        if (ox0 + 1 < 30) crow[1] = fmaxf(acc1, 0.f);
        if (ox0 + 2 < 30) crow[2] = fmaxf(acc2, 0.f);
        if (ox0 + 3 < 30) crow[3] = fmaxf(acc3, 0.f);
    }
    __syncthreads();

    // Phase 2: zero padded p1 [8][17][17] (2312) in R1, load w_b2(1152)+b_b2(16)
    for (int i = tid; i < 2312; i += 256) R1[i] = 0.f;
    for (int i = tid; i < 1168; i += 256)
        R1[2312 + i] = (i < 1152) ? w_b2[i] : b_b2[i - 1152];
    __syncthreads();
    // pool1: [8][15][15] into padded interior
    for (int i = tid; i < 1800; i += 256) {
        int c = i / 225, r = i % 225, y = r / 15, xw = r % 15;
        const float* c1r = R2 + c * 900 + (2 * y) * 30 + 2 * xw;
        float m = fmaxf(fmaxf(c1r[0], c1r[1]), fmaxf(c1r[30], c1r[31]));
        R1[c * 289 + (y + 1) * 17 + (xw + 1)] = m;
    }
    __syncthreads();

    // Phase 3: conv2 (3x3, pad1) + relu -> c2 [16][15][15] in R2
    // Work items: oc(16) x oy(15) x tiles(4) = 960
    for (int it = tid; it < 960; it += 256) {
        int oc = it / 60;
        int r = it % 60;
        int oy = r >> 2;
        int ox0 = (r & 3) * 4;
        float bias = R1[2312 + 1152 + oc];
        float acc0 = bias, acc1 = bias, acc2 = bias, acc3 = bias;
        const float* wb = R1 + 2312 + oc * 72;
        for (int ic = 0; ic < 8; ic++) {
            const float* prow = R1 + ic * 289 + oy * 17 + ox0;
            const float* wr = wb + ic * 9;
            #pragma unroll
            for (int ky = 0; ky < 3; ky++) {
                float xr[6];
                #pragma unroll
                for (int j = 0; j < 6; j++)
                    xr[j] = (ox0 + j < 17) ? prow[ky * 17 + j] : 0.f;
                #pragma unroll
                for (int kx = 0; kx < 3; kx++) {
                    float wv = wr[ky * 3 + kx];
                    acc0 += wv * xr[kx + 0];
                    acc1 += wv * xr[kx + 1];
                    acc2 += wv * xr[kx + 2];
                    acc3 += wv * xr[kx + 3];
                }
            }
        }
        float* crow = R2 + oc * 225 + oy * 15 + ox0;
        if (ox0 + 0 < 15) crow[0] = fmaxf(acc0, 0.f);
        if (ox0 + 1 < 15) crow[1] = fmaxf(acc1, 0.f);
        if (ox0 + 2 < 15) crow[2] = fmaxf(acc2, 0.f);
        if (ox0 + 3 < 15) crow[3] = fmaxf(acc3, 0.f);
    }
    __syncthreads();

    // Phase 4: pool2 -> p2 [16][7][7] at R1[0..784), load w_b3(512)+b_b3(32) at R1[784..)
    for (int i = tid; i < 544; i += 256)
        R1[784 + i] = (i < 512) ? w_b3[i] : b_b3[i - 512];
    for (int i = tid; i < 784; i += 256) {
        int c = i / 49, r = i % 49, y = r / 7, xw = r % 7;
        const float* c2r = R2 + c * 225 + (2 * y) * 15 + 2 * xw;
        R1[i] = fmaxf(fmaxf(c2r[0], c2r[1]), fmaxf(c2r[15], c2r[16]));
    }
    __syncthreads();

    // Phase 5: conv3 (1x1, pad1!) -> f [32][9][9]; border = bias. Write to global.
    float* gf = g_f + (size_t)b * 2592;
    for (int i = tid; i < 2592; i += 256) {
        int oc = i / 81, r = i % 81, oy = r / 9, ox = r % 9;
        float s = R1[784 + 512 + oc];
        if (oy >= 1 && oy <= 7 && ox >= 1 && ox <= 7) {
            const float* wr = R1 + 784 + oc * 16;
            const float* p2 = R1 + (oy - 1) * 7 + (ox - 1);
            #pragma unroll
            for (int ic = 0; ic < 16; ic++) s += wr[ic] * p2[ic * 49];
        }
        gf[i] = s;
    }
}

// ---------------------------------------------------------------------------
// Kernel B: adaptive-depth loop + final classifier. One CTA per sample.
// f stays in smem for all 8 iterations; early break when conf >= 0.9.
// smem floats: F 2592 | Q 1296 | WCF(transposed ic-major) 2048 | BCF 64 |
//              WCFC 1024 | WQ 512 | BQ 16 | WA 1536 | BA 32 | RED 80
// ---------------------------------------------------------------------------
__global__ __launch_bounds__(256) void loop_kernel(
    const float* __restrict__ g_f,
    const float* __restrict__ w_cf, const float* __restrict__ b_cf,
    const float* __restrict__ w_cfc, const float* __restrict__ b_cfc,
    const float* __restrict__ w_q, const float* __restrict__ b_q,
    const float* __restrict__ w_a, const float* __restrict__ b_a,
    const float* __restrict__ w_cls, const float* __restrict__ b_cls,
    float* __restrict__ out)
{
    __shared__ float sm[9200];
    __shared__ int s_flag;
    float* F    = sm;            // 2592
    float* Q    = sm + 2592;     // 1296
    float* WCF  = sm + 3888;     // 2048, stored [ic][oc] (ic*64+oc)
    float* BCF  = sm + 5936;     // 64
    float* WCFC = sm + 6000;     // 1024
    float* WQ   = sm + 7024;     // 512
    float* BQ   = sm + 7536;     // 16
    float* WA   = sm + 7552;     // 1536
    float* BA   = sm + 9088;     // 32
    float* RED  = sm + 9120;     // 80

    const int tid = threadIdx.x;
    const int b = blockIdx.x;
    const int wid = tid >> 5, lane = tid & 31;

    const float* gf = g_f + (size_t)b * 2592;
    for (int i = tid; i < 2592; i += 256) F[i] = gf[i];
    for (int i = tid; i < 2048; i += 256) {
        int oc = i >> 5, ic = i & 31;
        WCF[ic * 64 + oc] = w_cf[i];   // transpose: conflict-free oc-strided reads
    }
    for (int i = tid; i < 1024; i += 256) WCFC[i] = w_cfc[i];
    for (int i = tid; i < 512;  i += 256) WQ[i] = w_q[i];
    for (int i = tid; i < 1536; i += 256) WA[i] = w_a[i];
    if (tid < 64) BCF[tid] = b_cf[tid];
    if (tid < 16) BQ[tid] = b_q[tid];
    if (tid < 32) BA[tid] = b_a[tid];
    __syncthreads();
    const float bcfc = b_cfc[0];

    #pragma unroll 1
    for (int iter = 0; iter < 8; iter++) {
        // ---- confidence: threads 0..127 each handle 2 output channels, one pooled row
        float partial = 0.f;
        if (tid < 128) {
            int g  = tid >> 2;        // 0..31 -> oc pair
            int py = tid & 3;         // pooled row
            int oc0 = g * 2;
            float m0[4] = {0.f, 0.f, 0.f, 0.f};
            float m1[4] = {0.f, 0.f, 0.f, 0.f};
            #pragma unroll
            for (int dy = 0; dy < 2; dy++) {
                int y = 2 * py + dy;
                float bb0 = BCF[oc0], bb1 = BCF[oc0 + 1];
                float s0[8], s1[8];
                #pragma unroll
                for (int j = 0; j < 8; j++) { s0[j] = bb0; s1[j] = bb1; }
                const float* frow = F + y * 9;
                for (int ic = 0; ic < 32; ic++) {
                    float w0 = WCF[ic * 64 + oc0];
                    float w1 = WCF[ic * 64 + oc0 + 1];
                    const float* fr = frow + ic * 81;
                    #pragma unroll
                    for (int j = 0; j < 8; j++) {
                        float fv = fr[j];
                        s0[j] += w0 * fv;
                        s1[j] += w1 * fv;
                    }
                }
                #pragma unroll
                for (int px = 0; px < 4; px++) {
                    m0[px] = fmaxf(m0[px], fmaxf(s0[2 * px], s0[2 * px + 1]));
                    m1[px] = fmaxf(m1[px], fmaxf(s1[2 * px], s1[2 * px + 1]));
                }
            }
            #pragma unroll
            for (int px = 0; px < 4; px++) {
                partial += m0[px] * WCFC[oc0 * 16 + py * 4 + px];
                partial += m1[px] * WCFC[(oc0 + 1) * 16 + py * 4 + px];
            }
        }
        #pragma unroll
        for (int o = 16; o > 0; o >>= 1)
            partial += __shfl_down_sync(0xffffffffu, partial, o);
        if (lane == 0) RED[wid] = partial;
        __syncthreads();
        if (tid == 0) {
            float t = RED[0] + RED[1] + RED[2] + RED[3] +
                      RED[4] + RED[5] + RED[6] + RED[7] + bcfc;
            float conf = 1.f / (1.f + expf(-t));
            s_flag = (conf < 0.9f) ? 1 : 0;
        }
        __syncthreads();
        if (!s_flag) break;   // sample frozen: no further updates possible

        // ---- q = conv1x1 32->16 : items = 4 oc-groups x 81 pixels = 324
        #pragma unroll
        for (int u = 0; u < 2; u++) {
            int it = tid + u * 256;
            if (it < 324) {
                int ocg = it / 81, pix = it % 81;
                int oc0 = ocg * 4;
                float a0 = BQ[oc0], a1 = BQ[oc0 + 1], a2 = BQ[oc0 + 2], a3 = BQ[oc0 + 3];
                for (int ic = 0; ic < 32; ic++) {
                    float fv = F[ic * 81 + pix];
                    a0 += WQ[(oc0 + 0) * 32 + ic] * fv;
                    a1 += WQ[(oc0 + 1) * 32 + ic] * fv;
                    a2 += WQ[(oc0 + 2) * 32 + ic] * fv;
                    a3 += WQ[(oc0 + 3) * 32 + ic] * fv;
                }
                Q[(oc0 + 0) * 81 + pix] = a0;
                Q[(oc0 + 1) * 81 + pix] = a1;
                Q[(oc0 + 2) * 81 + pix] = a2;
                Q[(oc0 + 3) * 81 + pix] = a3;
            }
        }
        __syncthreads();

        // ---- a = tanh(conv1x1 [q;f] 48->32); buffer in regs, then f += a
        float av[3][4];
        #pragma unroll
        for (int u = 0; u < 3; u++) {
            int it = tid + u * 256;
            if (it < 648) {
                int ocg = it / 81, pix = it % 81;
                int oc0 = ocg * 4;
                float a0 = BA[oc0], a1 = BA[oc0 + 1], a2 = BA[oc0 + 2], a3 = BA[oc0 + 3];
                for (int c = 0; c < 16; c++) {
                    float qv = Q[c * 81 + pix];
                    a0 += WA[(oc0 + 0) * 48 + c] * qv;
                    a1 += WA[(oc0 + 1) * 48 + c] * qv;
                    a2 += WA[(oc0 + 2) * 48 + c] * qv;
                    a3 += WA[(oc0 + 3) * 48 + c] * qv;
                }
                for (int c = 0; c < 32; c++) {
                    float fv = F[c * 81 + pix];
                    a0 += WA[(oc0 + 0) * 48 + 16 + c] * fv;
                    a1 += WA[(oc0 + 1) * 48 + 16 + c] * fv;
                    a2 += WA[(oc0 + 2) * 48 + 16 + c] * fv;
                    a3 += WA[(oc0 + 3) * 48 + 16 + c] * fv;
                }
                av[u][0] = tanhf(a0);
                av[u][1] = tanhf(a1);
                av[u][2] = tanhf(a2);
                av[u][3] = tanhf(a3);
            }
        }
        __syncthreads();   // all a computed from old f before any write
        #pragma unroll
        for (int u = 0; u < 3; u++) {
            int it = tid + u * 256;
            if (it < 648) {
                int ocg = it / 81, pix = it % 81;
                int oc0 = ocg * 4;
                F[(oc0 + 0) * 81 + pix] += av[u][0];
                F[(oc0 + 1) * 81 + pix] += av[u][1];
                F[(oc0 + 2) * 81 + pix] += av[u][2];
                F[(oc0 + 3) * 81 + pix] += av[u][3];
            }
        }
        __syncthreads();
    }

    // ---- final classifier: out[b][k] = f . w_cls[k] + b_cls[k]
    float acc[10];
    #pragma unroll
    for (int k = 0; k < 10; k++) acc[k] = 0.f;
    for (int j = tid; j < 2592; j += 256) {
        float fv = F[j];
        #pragma unroll
        for (int k = 0; k < 10; k++) acc[k] += fv * w_cls[k * 2592 + j];
    }
    #pragma unroll
    for (int k = 0; k < 10; k++) {
        float v = acc[k];
        #pragma unroll
        for (int o = 16; o > 0; o >>= 1)
            v += __shfl_down_sync(0xffffffffu, v, o);
        if (lane == 0) RED[k * 8 + wid] = v;
    }
    __syncthreads();
    if (tid < 10) {
        float t = b_cls[tid];
        #pragma unroll
        for (int w = 0; w < 8; w++) t += RED[tid * 8 + w];
        out[(size_t)b * 10 + tid] = t;
    }
}

// ---------------------------------------------------------------------------
extern "C" void kernel_launch(void* const* d_in, const int* in_sizes, int n_in,
                              void* d_out, int out_size)
{
    const float* x     = (const float*)d_in[0];
    const float* w_b1  = (const float*)d_in[1];
    const float* b_b1  = (const float*)d_in[2];
    const float* w_b2  = (const float*)d_in[3];
    const float* b_b2  = (const float*)d_in[4];
    const float* w_b3  = (const float*)d_in[5];
    const float* b_b3  = (const float*)d_in[6];
    const float* w_cf  = (const float*)d_in[7];
    const float* b_cf  = (const float*)d_in[8];
    const float* w_cfc = (const float*)d_in[9];
    const float* b_cfc = (const float*)d_in[10];
    const float* w_q   = (const float*)d_in[11];
    const float* b_q   = (const float*)d_in[12];
    const float* w_a   = (const float*)d_in[13];
    const float* b_a   = (const float*)d_in[14];
    const float* w_cls = (const float*)d_in[15];
    const float* b_cls = (const float*)d_in[16];

    int B = in_sizes[0] / 3072;
    if (B > 8192) B = 8192;

    float* g_f = nullptr;
    cudaGetSymbolAddress((void**)&g_f, g_f_scratch);

    base_kernel<<<B, 256>>>(x, w_b1, b_b1, w_b2, b_b2, w_b3, b_b3, g_f);
    loop_kernel<<<B, 256>>>(g_f, w_cf, b_cf, w_cfc, b_cfc,
                            w_q, b_q, w_a, b_a, w_cls, b_cls,
                            (float*)d_out);
}

// round 7
// speedup vs baseline: 1.0089x; 1.0089x over previous
#include <cuda_runtime.h>
#include <math.h>

typedef unsigned long long u64;

__device__ __forceinline__ u64 dup2(float x) {
    u64 r; asm("mov.b64 %0, {%1, %1};" : "=l"(r) : "f"(x)); return r;
}
__device__ __forceinline__ void unpack2(u64 v, float& x, float& y) {
    asm("mov.b64 {%0, %1}, %2;" : "=f"(x), "=f"(y) : "l"(v));
}
__device__ __forceinline__ u64 ffma2(u64 a, u64 b, u64 c) {
    u64 d; asm("fma.rn.f32x2 %0, %1, %2, %3;" : "=l"(d) : "l"(a), "l"(b), "l"(c));
    return d;
}
__device__ __forceinline__ float fast_tanh(float x) {
    float e = __expf(2.f * x);
    return 1.f - __fdividef(2.f, e + 1.f);
}

// Scratch for the base-module output f: [8192][32][9][9]
static __device__ float g_f_scratch[8192 * 2592];

// ---------------------------------------------------------------------------
// Kernel A: base module (unchanged from R2). One CTA per sample.
// ---------------------------------------------------------------------------
__global__ __launch_bounds__(256) void base_kernel(
    const float* __restrict__ x,
    const float* __restrict__ w_b1, const float* __restrict__ b_b1,
    const float* __restrict__ w_b2, const float* __restrict__ b_b2,
    const float* __restrict__ w_b3, const float* __restrict__ b_b3,
    float* __restrict__ g_f)
{
    __shared__ float sm[3480 + 7200 + 608];
    float* R1 = sm;
    float* R2 = sm + 3480;
    float* R3 = sm + 3480 + 7200;
    const int tid = threadIdx.x;
    const int b = blockIdx.x;
    const float* xb = x + (size_t)b * 3072;

    for (int i = tid; i < 3468; i += 256) R1[i] = 0.f;
    for (int i = tid; i < 608; i += 256) R3[i] = (i < 600) ? w_b1[i] : b_b1[i - 600];
    __syncthreads();
    for (int i = tid; i < 3072; i += 256) {
        int ic = i >> 10, r = i & 1023, iy = r >> 5, ix = r & 31;
        R1[ic * 1156 + (iy + 1) * 34 + (ix + 1)] = xb[i];
    }
    __syncthreads();

    for (int it = tid; it < 1920; it += 256) {
        int oc = it / 240;
        int r = it % 240;
        int oy = r >> 3;
        int ox0 = (r & 7) * 4;
        float bias = R3[600 + oc];
        float acc0 = bias, acc1 = bias, acc2 = bias, acc3 = bias;
        const float* wb = R3 + oc * 75;
        for (int ic = 0; ic < 3; ic++) {
            const float* xrow = R1 + ic * 1156 + oy * 34 + ox0;
            const float* wr = wb + ic * 25;
            #pragma unroll
            for (int ky = 0; ky < 5; ky++) {
                float xr[8];
                #pragma unroll
                for (int j = 0; j < 8; j++)
                    xr[j] = (ox0 + j < 34) ? xrow[ky * 34 + j] : 0.f;
                #pragma unroll
                for (int kx = 0; kx < 5; kx++) {
                    float wv = wr[ky * 5 + kx];
                    acc0 += wv * xr[kx + 0];
                    acc1 += wv * xr[kx + 1];
                    acc2 += wv * xr[kx + 2];
                    acc3 += wv * xr[kx + 3];
                }
            }
        }
        float* crow = R2 + oc * 900 + oy * 30 + ox0;
        if (ox0 + 0 < 30) crow[0] = fmaxf(acc0, 0.f);
        if (ox0 + 1 < 30) crow[1] = fmaxf(acc1, 0.f);
        if (ox0 + 2 < 30) crow[2] = fmaxf(acc2, 0.f);
        if (ox0 + 3 < 30) crow[3] = fmaxf(acc3, 0.f);
    }
    __syncthreads();

    for (int i = tid; i < 2312; i += 256) R1[i] = 0.f;
    for (int i = tid; i < 1168; i += 256)
        R1[2312 + i] = (i < 1152) ? w_b2[i] : b_b2[i - 1152];
    __syncthreads();
    for (int i = tid; i < 1800; i += 256) {
        int c = i / 225, r = i % 225, y = r / 15, xw = r % 15;
        const float* c1r = R2 + c * 900 + (2 * y) * 30 + 2 * xw;
        float m = fmaxf(fmaxf(c1r[0], c1r[1]), fmaxf(c1r[30], c1r[31]));
        R1[c * 289 + (y + 1) * 17 + (xw + 1)] = m;
    }
    __syncthreads();

    for (int it = tid; it < 960; it += 256) {
        int oc = it / 60;
        int r = it % 60;
        int oy = r >> 2;
        int ox0 = (r & 3) * 4;
        float bias = R1[2312 + 1152 + oc];
        float acc0 = bias, acc1 = bias, acc2 = bias, acc3 = bias;
        const float* wb = R1 + 2312 + oc * 72;
        for (int ic = 0; ic < 8; ic++) {
            const float* prow = R1 + ic * 289 + oy * 17 + ox0;
            const float* wr = wb + ic * 9;
            #pragma unroll
            for (int ky = 0; ky < 3; ky++) {
                float xr[6];
                #pragma unroll
                for (int j = 0; j < 6; j++)
                    xr[j] = (ox0 + j < 17) ? prow[ky * 17 + j] : 0.f;
                #pragma unroll
                for (int kx = 0; kx < 3; kx++) {
                    float wv = wr[ky * 3 + kx];
                    acc0 += wv * xr[kx + 0];
                    acc1 += wv * xr[kx + 1];
                    acc2 += wv * xr[kx + 2];
                    acc3 += wv * xr[kx + 3];
                }
            }
        }
        float* crow = R2 + oc * 225 + oy * 15 + ox0;
        if (ox0 + 0 < 15) crow[0] = fmaxf(acc0, 0.f);
        if (ox0 + 1 < 15) crow[1] = fmaxf(acc1, 0.f);
        if (ox0 + 2 < 15) crow[2] = fmaxf(acc2, 0.f);
        if (ox0 + 3 < 15) crow[3] = fmaxf(acc3, 0.f);
    }
    __syncthreads();

    for (int i = tid; i < 544; i += 256)
        R1[784 + i] = (i < 512) ? w_b3[i] : b_b3[i - 512];
    for (int i = tid; i < 784; i += 256) {
        int c = i / 49, r = i % 49, y = r / 7, xw = r % 7;
        const float* c2r = R2 + c * 225 + (2 * y) * 15 + 2 * xw;
        R1[i] = fmaxf(fmaxf(c2r[0], c2r[1]), fmaxf(c2r[15], c2r[16]));
    }
    __syncthreads();

    float* gf = g_f + (size_t)b * 2592;
    for (int i = tid; i < 2592; i += 256) {
        int oc = i / 81, r = i % 81, oy = r / 9, ox = r % 9;
        float s = R1[784 + 512 + oc];
        if (oy >= 1 && oy <= 7 && ox >= 1 && ox <= 7) {
            const float* wr = R1 + 784 + oc * 16;
            const float* p2 = R1 + (oy - 1) * 7 + (ox - 1);
            #pragma unroll
            for (int ic = 0; ic < 16; ic++) s += wr[ic] * p2[ic * 49];
        }
        gf[i] = s;
    }
}

// ---------------------------------------------------------------------------
// Kernel B v2: adaptive loop + classifier, f32x2 packed FMA.
// F layout: [32 ic][96], where col = y*10 + x (row stride 10, even => float2
// aligned); cols 9,19,...,89 and 90..95 are padding (bounded garbage, never
// read for valid outputs). Q layout: [16][96], same addressing.
// All loop weights transposed to [ic][oc] so a warp's weight loads are
// consecutive and activation loads are lane-broadcasts (crossbar-free).
// smem floats:
//   F 0..3072 | Q 3072..4608 | WCF 4608..6656 | WCFC 6656..7680 |
//   WQ 7680..8192 | WA 8192..9728 | BCF 9728..9792 | BQ 9792..9808 |
//   BA 9808..9840 | RED 9840..9920
// ---------------------------------------------------------------------------
__global__ __launch_bounds__(256) void loop_kernel(
    const float* __restrict__ g_f,
    const float* __restrict__ w_cf, const float* __restrict__ b_cf,
    const float* __restrict__ w_cfc, const float* __restrict__ b_cfc,
    const float* __restrict__ w_q, const float* __restrict__ b_q,
    const float* __restrict__ w_a, const float* __restrict__ b_a,
    const float* __restrict__ w_cls, const float* __restrict__ b_cls,
    float* __restrict__ out)
{
    __shared__ __align__(16) float sm[9920];
    __shared__ int s_flag;
    float* F    = sm;
    float* Q    = sm + 3072;
    float* WCF  = sm + 4608;   // [ic][64]
    float* WCFC = sm + 6656;   // [64][16]
    float* WQ   = sm + 7680;   // [ic][16]
    float* WA   = sm + 8192;   // [ic 0..47][32]
    float* BCF  = sm + 9728;
    float* BQ   = sm + 9792;
    float* BA   = sm + 9808;
    float* RED  = sm + 9840;

    const int tid = threadIdx.x;
    const int b = blockIdx.x;
    const int wid = tid >> 5, lane = tid & 31;

    // ---- loads + transposes
    for (int i = tid; i < 3072; i += 256) F[i] = 0.f;
    for (int i = tid; i < 2048; i += 256) {
        int oc = i >> 5, ic = i & 31;
        WCF[ic * 64 + oc] = w_cf[i];
    }
    for (int i = tid; i < 1024; i += 256) WCFC[i] = w_cfc[i];
    for (int i = tid; i < 512; i += 256) {
        int oc = i >> 5, ic = i & 31;
        WQ[ic * 16 + oc] = w_q[i];
    }
    for (int i = tid; i < 1536; i += 256) {
        int oc = i / 48, ic = i % 48;
        WA[ic * 32 + oc] = w_a[i];
    }
    if (tid < 64) BCF[tid] = b_cf[tid];
    if (tid < 16) BQ[tid] = b_q[tid];
    if (tid < 32) BA[tid] = b_a[tid];
    __syncthreads();
    const float* gf = g_f + (size_t)b * 2592;
    for (int i = tid; i < 2592; i += 256) {
        int ic = i / 81, px = i % 81;
        int y = px / 9, xx = px % 9;
        F[ic * 96 + y * 10 + xx] = gf[i];
    }
    __syncthreads();
    const float bcfc = b_cfc[0];

    #pragma unroll 1
    for (int iter = 0; iter < 8; iter++) {
        // ===== Phase 1: conf (tid 0..127) + q conv (tid 128..223) =====
        if (tid < 128) {
            // item: ocg = tid&31 (2 oc), py = tid>>5 (pooled row)
            int ocg = tid & 31, py = tid >> 5;
            int oc0 = ocg << 1;
            u64 a0[8], a1[8];  // [0..3]=row 2py pairs, [4..7]=row 2py+1 pairs
            u64 bb0 = dup2(BCF[oc0]), bb1 = dup2(BCF[oc0 + 1]);
            #pragma unroll
            for (int j = 0; j < 8; j++) { a0[j] = bb0; a1[j] = bb1; }
            const float* fb = F + py * 20;
            #pragma unroll 4
            for (int ic = 0; ic < 32; ic++) {
                u64 w0 = dup2(WCF[ic * 64 + oc0]);
                u64 w1 = dup2(WCF[ic * 64 + oc0 + 1]);
                const u64* r0 = (const u64*)(fb + ic * 96);
                const u64* r1 = (const u64*)(fb + ic * 96 + 10);
                #pragma unroll
                for (int j = 0; j < 4; j++) {
                    u64 f0 = r0[j], f1 = r1[j];
                    a0[j]     = ffma2(w0, f0, a0[j]);
                    a0[4 + j] = ffma2(w0, f1, a0[4 + j]);
                    a1[j]     = ffma2(w1, f0, a1[j]);
                    a1[4 + j] = ffma2(w1, f1, a1[4 + j]);
                }
            }
            float partial = 0.f;
            #pragma unroll
            for (int j = 0; j < 4; j++) {
                float x0, y0, x1, y1;
                unpack2(a0[j], x0, y0); unpack2(a0[4 + j], x1, y1);
                float p = fmaxf(fmaxf(fmaxf(x0, y0), fmaxf(x1, y1)), 0.f);
                partial += p * WCFC[oc0 * 16 + py * 4 + j];
                unpack2(a1[j], x0, y0); unpack2(a1[4 + j], x1, y1);
                p = fmaxf(fmaxf(fmaxf(x0, y0), fmaxf(x1, y1)), 0.f);
                partial += p * WCFC[(oc0 + 1) * 16 + py * 4 + j];
            }
            #pragma unroll
            for (int o = 16; o > 0; o >>= 1)
                partial += __shfl_down_sync(0xffffffffu, partial, o);
            if (lane == 0) RED[wid] = partial;
        } else if (tid < 224) {
            // q conv: j = tid-128: ocg = j&7 (2 oc), pt = j>>3 (0..11)
            int j = tid - 128;
            int ocg = j & 7, pt = j >> 3;
            int oc0 = ocg << 1, col = pt << 3;
            u64 q0[4], q1[4];
            u64 b0 = dup2(BQ[oc0]), b1 = dup2(BQ[oc0 + 1]);
            #pragma unroll
            for (int k = 0; k < 4; k++) { q0[k] = b0; q1[k] = b1; }
            #pragma unroll 4
            for (int ic = 0; ic < 32; ic++) {
                u64 w0 = dup2(WQ[ic * 16 + oc0]);
                u64 w1 = dup2(WQ[ic * 16 + oc0 + 1]);
                const u64* fr = (const u64*)(F + ic * 96 + col);
                #pragma unroll
                for (int k = 0; k < 4; k++) {
                    u64 fv = fr[k];
                    q0[k] = ffma2(w0, fv, q0[k]);
                    q1[k] = ffma2(w1, fv, q1[k]);
                }
            }
            u64* qd0 = (u64*)(Q + oc0 * 96 + col);
            u64* qd1 = (u64*)(Q + (oc0 + 1) * 96 + col);
            #pragma unroll
            for (int k = 0; k < 4; k++) { qd0[k] = q0[k]; qd1[k] = q1[k]; }
        }
        __syncthreads();
        if (tid == 0) {
            float t = RED[0] + RED[1] + RED[2] + RED[3] + bcfc;
            float conf = 1.f / (1.f + expf(-t));
            s_flag = (conf < 0.9f) ? 1 : 0;
        }
        __syncthreads();
        if (!s_flag) break;

        // ===== Phase 2: a = tanh(conv48->32) on [Q;F], then F += a =====
        float t0[8], t1[8];
        int oc0 = 0, col = 0;
        const bool act = tid < 192;
        if (act) {
            int ocg = tid & 15, pt = tid >> 4;   // 16 ocg x 12 ptiles
            oc0 = ocg << 1; col = pt << 3;
            u64 s0[4], s1[4];
            u64 b0 = dup2(BA[oc0]), b1 = dup2(BA[oc0 + 1]);
            #pragma unroll
            for (int k = 0; k < 4; k++) { s0[k] = b0; s1[k] = b1; }
            #pragma unroll 4
            for (int ic = 0; ic < 16; ic++) {
                u64 w0 = dup2(WA[ic * 32 + oc0]);
                u64 w1 = dup2(WA[ic * 32 + oc0 + 1]);
                const u64* qr = (const u64*)(Q + ic * 96 + col);
                #pragma unroll
                for (int k = 0; k < 4; k++) {
                    u64 qv = qr[k];
                    s0[k] = ffma2(w0, qv, s0[k]);
                    s1[k] = ffma2(w1, qv, s1[k]);
                }
            }
            #pragma unroll 4
            for (int ic = 0; ic < 32; ic++) {
                u64 w0 = dup2(WA[(16 + ic) * 32 + oc0]);
                u64 w1 = dup2(WA[(16 + ic) * 32 + oc0 + 1]);
                const u64* fr = (const u64*)(F + ic * 96 + col);
                #pragma unroll
                for (int k = 0; k < 4; k++) {
                    u64 fv = fr[k];
                    s0[k] = ffma2(w0, fv, s0[k]);
                    s1[k] = ffma2(w1, fv, s1[k]);
                }
            }
            #pragma unroll
            for (int k = 0; k < 4; k++) {
                float xa, xb2;
                unpack2(s0[k], xa, xb2);
                t0[2 * k] = fast_tanh(xa); t0[2 * k + 1] = fast_tanh(xb2);
                unpack2(s1[k], xa, xb2);
                t1[2 * k] = fast_tanh(xa); t1[2 * k + 1] = fast_tanh(xb2);
            }
        }
        __syncthreads();   // all reads of old F complete before any write
        if (act) {
            float2* fd0 = (float2*)(F + oc0 * 96 + col);
            float2* fd1 = (float2*)(F + (oc0 + 1) * 96 + col);
            #pragma unroll
            for (int k = 0; k < 4; k++) {
                float2 v = fd0[k]; v.x += t0[2 * k]; v.y += t0[2 * k + 1]; fd0[k] = v;
                float2 w = fd1[k]; w.x += t1[2 * k]; w.y += t1[2 * k + 1]; fd1[k] = w;
            }
        }
        __syncthreads();
    }

    // ===== Final classifier =====
    float acc[10];
    #pragma unroll
    for (int k = 0; k < 10; k++) acc[k] = 0.f;
    for (int j = tid; j < 2592; j += 256) {
        int ic = j / 81, px = j % 81;
        float fv = F[ic * 96 + (px / 9) * 10 + (px % 9)];
        #pragma unroll
        for (int k = 0; k < 10; k++) acc[k] += fv * w_cls[k * 2592 + j];
    }
    #pragma unroll
    for (int k = 0; k < 10; k++) {
        float v = acc[k];
        #pragma unroll
        for (int o = 16; o > 0; o >>= 1)
            v += __shfl_down_sync(0xffffffffu, v, o);
        if (lane == 0) RED[k * 8 + wid] = v;
    }
    __syncthreads();
    if (tid < 10) {
        float t = b_cls[tid];
        #pragma unroll
        for (int w = 0; w < 8; w++) t += RED[tid * 8 + w];
        out[(size_t)b * 10 + tid] = t;
    }
}

// ---------------------------------------------------------------------------
extern "C" void kernel_launch(void* const* d_in, const int* in_sizes, int n_in,
                              void* d_out, int out_size)
{
    const float* x     = (const float*)d_in[0];
    const float* w_b1  = (const float*)d_in[1];
    const float* b_b1  = (const float*)d_in[2];
    const float* w_b2  = (const float*)d_in[3];
    const float* b_b2  = (const float*)d_in[4];
    const float* w_b3  = (const float*)d_in[5];
    const float* b_b3  = (const float*)d_in[6];
    const float* w_cf  = (const float*)d_in[7];
    const float* b_cf  = (const float*)d_in[8];
    const float* w_cfc = (const float*)d_in[9];
    const float* b_cfc = (const float*)d_in[10];
    const float* w_q   = (const float*)d_in[11];
    const float* b_q   = (const float*)d_in[12];
    const float* w_a   = (const float*)d_in[13];
    const float* b_a   = (const float*)d_in[14];
    const float* w_cls = (const float*)d_in[15];
    const float* b_cls = (const float*)d_in[16];

    int B = in_sizes[0] / 3072;
    if (B > 8192) B = 8192;

    float* g_f = nullptr;
    cudaGetSymbolAddress((void**)&g_f, g_f_scratch);

    base_kernel<<<B, 256>>>(x, w_b1, b_b1, w_b2, b_b2, w_b3, b_b3, g_f);
    loop_kernel<<<B, 256>>>(g_f, w_cf, b_cf, w_cfc, b_cfc,
                            w_q, b_q, w_a, b_a, w_cls, b_cls,
                            (float*)d_out);
}

// round 9
// speedup vs baseline: 1.2637x; 1.2526x over previous
#include <cuda_runtime.h>
#include <math.h>

typedef unsigned long long u64;

__device__ __forceinline__ u64 dup2(float x) {
    u64 r; asm("mov.b64 %0, {%1, %1};" : "=l"(r) : "f"(x)); return r;
}
__device__ __forceinline__ void unpack2(u64 v, float& x, float& y) {
    asm("mov.b64 {%0, %1}, %2;" : "=f"(x), "=f"(y) : "l"(v));
}
__device__ __forceinline__ u64 ffma2(u64 a, u64 b, u64 c) {
    u64 d; asm("fma.rn.f32x2 %0, %1, %2, %3;" : "=l"(d) : "l"(a), "l"(b), "l"(c));
    return d;
}
__device__ __forceinline__ float fast_tanh(float x) {
    float e = __expf(2.f * x);
    return 1.f - __fdividef(2.f, e + 1.f);
}

// Scratch for the base-module output f: [8192][32][9][9]
static __device__ float g_f_scratch[8192 * 2592];

// ---------------------------------------------------------------------------
// Kernel A: base module. One CTA per sample.
// Input padded to [3][34][36] (row stride 36 -> every row 16B-aligned so the
// conv1 8-wide window is two float4 LDS instead of eight scalar LDS).
// ---------------------------------------------------------------------------
__global__ __launch_bounds__(256) void base_kernel(
    const float* __restrict__ x,
    const float* __restrict__ w_b1, const float* __restrict__ b_b1,
    const float* __restrict__ w_b2, const float* __restrict__ b_b2,
    const float* __restrict__ w_b3, const float* __restrict__ b_b3,
    float* __restrict__ g_f)
{
    __shared__ __align__(16) float sm[3696 + 7200 + 608];
    float* R1 = sm;                  // 3696: padded x [3][34][36] / p1+w2 / p2+w3
    float* R2 = sm + 3696;           // 7200: c1 / c2
    float* R3 = sm + 3696 + 7200;    // 608:  w_b1 + b_b1
    const int tid = threadIdx.x;
    const int b = blockIdx.x;
    const float* xb = x + (size_t)b * 3072;

    // Phase 0: zero-pad input to [3][34][36], load w_b1(600)+b_b1(8)
    for (int i = tid; i < 3672; i += 256) R1[i] = 0.f;
    for (int i = tid; i < 608; i += 256) R3[i] = (i < 600) ? w_b1[i] : b_b1[i - 600];
    __syncthreads();
    for (int i = tid; i < 3072; i += 256) {
        int ic = i >> 10, r = i & 1023, iy = r >> 5, ix = r & 31;
        R1[ic * 1224 + (iy + 1) * 36 + (ix + 1)] = xb[i];
    }
    __syncthreads();

    // Phase 1: conv1 (5x5, pad1) + relu -> c1 [8][30][30] in R2
    for (int it = tid; it < 1920; it += 256) {
        int oc = it / 240;
        int r = it % 240;
        int oy = r >> 3;
        int ox0 = (r & 7) * 4;
        float bias = R3[600 + oc];
        float acc0 = bias, acc1 = bias, acc2 = bias, acc3 = bias;
        const float* wb = R3 + oc * 75;
        for (int ic = 0; ic < 3; ic++) {
            const float* xrow = R1 + ic * 1224 + oy * 36 + ox0;
            const float* wr = wb + ic * 25;
            #pragma unroll
            for (int ky = 0; ky < 5; ky++) {
                float4 xa = *(const float4*)(xrow + ky * 36);
                float4 xc = *(const float4*)(xrow + ky * 36 + 4);
                float xr[8] = {xa.x, xa.y, xa.z, xa.w, xc.x, xc.y, xc.z, xc.w};
                #pragma unroll
                for (int kx = 0; kx < 5; kx++) {
                    float wv = wr[ky * 5 + kx];
                    acc0 += wv * xr[kx + 0];
                    acc1 += wv * xr[kx + 1];
                    acc2 += wv * xr[kx + 2];
                    acc3 += wv * xr[kx + 3];
                }
            }
        }
        float* crow = R2 + oc * 900 + oy * 30 + ox0;
        if (ox0 + 0 < 30) crow[0] = fmaxf(acc0, 0.f);
        if (ox0 + 1 < 30) crow[1] = fmaxf(acc1, 0.f);
        if (ox0 + 2 < 30) crow[2] = fmaxf(acc2, 0.f);
        if (ox0 + 3 < 30) crow[3] = fmaxf(acc3, 0.f);
    }
    __syncthreads();

    // Phase 2: zero padded p1 [8][17][17] (2312) in R1, load w_b2(1152)+b_b2(16)
    for (int i = tid; i < 2312; i += 256) R1[i] = 0.f;
    for (int i = tid; i < 1168; i += 256)
        R1[2312 + i] = (i < 1152) ? w_b2[i] : b_b2[i - 1152];
    __syncthreads();
    for (int i = tid; i < 1800; i += 256) {
        int c = i / 225, r = i % 225, y = r / 15, xw = r % 15;
        const float* c1r = R2 + c * 900 + (2 * y) * 30 + 2 * xw;
        float m = fmaxf(fmaxf(c1r[0], c1r[1]), fmaxf(c1r[30], c1r[31]));
        R1[c * 289 + (y + 1) * 17 + (xw + 1)] = m;
    }
    __syncthreads();

    // Phase 3: conv2 (3x3, pad1) + relu -> c2 [16][15][15] in R2
    for (int it = tid; it < 960; it += 256) {
        int oc = it / 60;
        int r = it % 60;
        int oy = r >> 2;
        int ox0 = (r & 3) * 4;
        float bias = R1[2312 + 1152 + oc];
        float acc0 = bias, acc1 = bias, acc2 = bias, acc3 = bias;
        const float* wb = R1 + 2312 + oc * 72;
        for (int ic = 0; ic < 8; ic++) {
            const float* prow = R1 + ic * 289 + oy * 17 + ox0;
            const float* wr = wb + ic * 9;
            #pragma unroll
            for (int ky = 0; ky < 3; ky++) {
                float xr[6];
                #pragma unroll
                for (int j = 0; j < 6; j++)
                    xr[j] = (ox0 + j < 17) ? prow[ky * 17 + j] : 0.f;
                #pragma unroll
                for (int kx = 0; kx < 3; kx++) {
                    float wv = wr[ky * 3 + kx];
                    acc0 += wv * xr[kx + 0];
                    acc1 += wv * xr[kx + 1];
                    acc2 += wv * xr[kx + 2];
                    acc3 += wv * xr[kx + 3];
                }
            }
        }
        float* crow = R2 + oc * 225 + oy * 15 + ox0;
        if (ox0 + 0 < 15) crow[0] = fmaxf(acc0, 0.f);
        if (ox0 + 1 < 15) crow[1] = fmaxf(acc1, 0.f);
        if (ox0 + 2 < 15) crow[2] = fmaxf(acc2, 0.f);
        if (ox0 + 3 < 15) crow[3] = fmaxf(acc3, 0.f);
    }
    __syncthreads();

    // Phase 4: pool2 -> p2 [16][7][7], load w_b3(512)+b_b3(32)
    for (int i = tid; i < 544; i += 256)
        R1[784 + i] = (i < 512) ? w_b3[i] : b_b3[i - 512];
    for (int i = tid; i < 784; i += 256) {
        int c = i / 49, r = i % 49, y = r / 7, xw = r % 7;
        const float* c2r = R2 + c * 225 + (2 * y) * 15 + 2 * xw;
        R1[i] = fmaxf(fmaxf(c2r[0], c2r[1]), fmaxf(c2r[15], c2r[16]));
    }
    __syncthreads();

    // Phase 5: conv3 (1x1, pad1) -> f [32][9][9] to global
    float* gf = g_f + (size_t)b * 2592;
    for (int i = tid; i < 2592; i += 256) {
        int oc = i / 81, r = i % 81, oy = r / 9, ox = r % 9;
        float s = R1[784 + 512 + oc];
        if (oy >= 1 && oy <= 7 && ox >= 1 && ox <= 7) {
            const float* wr = R1 + 784 + oc * 16;
            const float* p2 = R1 + (oy - 1) * 7 + (ox - 1);
            #pragma unroll
            for (int ic = 0; ic < 16; ic++) s += wr[ic] * p2[ic * 49];
        }
        gf[i] = s;
    }
}

// ---------------------------------------------------------------------------
// Kernel B v3: adaptive loop + classifier.
// F layout: [32 ic][108], col = y*12 + x. Row stride 12 => EVERY row start is
// 16B-aligned, so all activation reads are LDS.128 and weight pairs LDS.64.
// Padding cols (x=9..11, rows 9..) carry bounded garbage, never read as valid.
// Work tiles = one padded row (12 px = 3 float4 = 6 f32x2 lanes).
// ---------------------------------------------------------------------------
__global__ __launch_bounds__(256, 4) void loop_kernel(
    const float* __restrict__ g_f,
    const float* __restrict__ w_cf, const float* __restrict__ b_cf,
    const float* __restrict__ w_cfc, const float* __restrict__ b_cfc,
    const float* __restrict__ w_q, const float* __restrict__ b_q,
    const float* __restrict__ w_a, const float* __restrict__ b_a,
    const float* __restrict__ w_cls, const float* __restrict__ b_cls,
    float* __restrict__ out)
{
    __shared__ __align__(16) float sm[10496];
    __shared__ int s_flag;
    float* F    = sm;           // 3456 = 32*108
    float* Q    = sm + 3456;    // 1728 = 16*108
    float* WCF  = sm + 5184;    // [ic][64] (oc pairs adjacent)
    float* WCFC = sm + 7232;    // [64][16]
    float* WQ   = sm + 8256;    // [ic][16]
    float* WA   = sm + 8768;    // [ic 0..47][32]
    float* BCF  = sm + 10304;   // 64
    float* BQ   = sm + 10368;   // 16
    float* BA   = sm + 10384;   // 32
    float* RED  = sm + 10416;   // 80

    const int tid = threadIdx.x;
    const int b = blockIdx.x;
    const int wid = tid >> 5, lane = tid & 31;

    // ---- loads + transposes
    for (int i = tid; i < 3456; i += 256) F[i] = 0.f;
    for (int i = tid; i < 2048; i += 256) {
        int oc = i >> 5, ic = i & 31;
        WCF[ic * 64 + oc] = w_cf[i];
    }
    for (int i = tid; i < 1024; i += 256) WCFC[i] = w_cfc[i];
    for (int i = tid; i < 512; i += 256) {
        int oc = i >> 5, ic = i & 31;
        WQ[ic * 16 + oc] = w_q[i];
    }
    for (int i = tid; i < 1536; i += 256) {
        int oc = i / 48, ic = i % 48;
        WA[ic * 32 + oc] = w_a[i];
    }
    if (tid < 64) BCF[tid] = b_cf[tid];
    if (tid < 16) BQ[tid] = b_q[tid];
    if (tid < 32) BA[tid] = b_a[tid];
    __syncthreads();
    const float* gf = g_f + (size_t)b * 2592;
    for (int i = tid; i < 2592; i += 256) {
        int ic = i / 81, px = i % 81;
        F[ic * 108 + (px / 9) * 12 + (px % 9)] = gf[i];
    }
    __syncthreads();
    const float bcfc = b_cfc[0];

    #pragma unroll 1
    for (int iter = 0; iter < 8; iter++) {
        // ===== Phase 1: conf (tid 0..127) + q conv (tid 128..199) =====
        if (tid < 128) {
            int ocg = tid & 31, py = tid >> 5;   // 2 oc, one pooled row
            int oc0 = ocg << 1;
            u64 a0[8], a1[8];  // [0..3]=row 2py col-pairs, [4..7]=row 2py+1
            u64 bb0 = dup2(BCF[oc0]), bb1 = dup2(BCF[oc0 + 1]);
            #pragma unroll
            for (int j = 0; j < 8; j++) { a0[j] = bb0; a1[j] = bb1; }
            const float* fb = F + py * 24;
            #pragma unroll 4
            for (int ic = 0; ic < 32; ic++) {
                const float* base = fb + ic * 108;
                ulonglong2 A0 = *(const ulonglong2*)(base);       // cols 0-3
                ulonglong2 A1 = *(const ulonglong2*)(base + 4);   // cols 4-7
                ulonglong2 B0 = *(const ulonglong2*)(base + 12);  // next row
                ulonglong2 B1 = *(const ulonglong2*)(base + 16);
                u64 wp = *(const u64*)(WCF + ic * 64 + 2 * ocg);
                float w0f, w1f; unpack2(wp, w0f, w1f);
                u64 w0 = dup2(w0f), w1 = dup2(w1f);
                a0[0] = ffma2(w0, A0.x, a0[0]);
                a0[1] = ffma2(w0, A0.y, a0[1]);
                a0[2] = ffma2(w0, A1.x, a0[2]);
                a0[3] = ffma2(w0, A1.y, a0[3]);
                a0[4] = ffma2(w0, B0.x, a0[4]);
                a0[5] = ffma2(w0, B0.y, a0[5]);
                a0[6] = ffma2(w0, B1.x, a0[6]);
                a0[7] = ffma2(w0, B1.y, a0[7]);
                a1[0] = ffma2(w1, A0.x, a1[0]);
                a1[1] = ffma2(w1, A0.y, a1[1]);
                a1[2] = ffma2(w1, A1.x, a1[2]);
                a1[3] = ffma2(w1, A1.y, a1[3]);
                a1[4] = ffma2(w1, B0.x, a1[4]);
                a1[5] = ffma2(w1, B0.y, a1[5]);
                a1[6] = ffma2(w1, B1.x, a1[6]);
                a1[7] = ffma2(w1, B1.y, a1[7]);
            }
            float partial = 0.f;
            #pragma unroll
            for (int j = 0; j < 4; j++) {
                float x0, y0, x1, y1;
                unpack2(a0[j], x0, y0); unpack2(a0[4 + j], x1, y1);
                float p = fmaxf(fmaxf(fmaxf(x0, y0), fmaxf(x1, y1)), 0.f);
                partial += p * WCFC[oc0 * 16 + py * 4 + j];
                unpack2(a1[j], x0, y0); unpack2(a1[4 + j], x1, y1);
                p = fmaxf(fmaxf(fmaxf(x0, y0), fmaxf(x1, y1)), 0.f);
                partial += p * WCFC[(oc0 + 1) * 16 + py * 4 + j];
            }
            #pragma unroll
            for (int o = 16; o > 0; o >>= 1)
                partial += __shfl_down_sync(0xffffffffu, partial, o);
            if (lane == 0) RED[wid] = partial;
        } else if (tid < 200) {
            // q conv: 8 oc-pairs x 9 row-tiles = 72 threads
            int t = tid - 128;
            int ocg = t & 7, rt = t >> 3;
            int oc0 = ocg << 1, col = rt * 12;
            u64 q0[6], q1[6];
            u64 b0 = dup2(BQ[oc0]), b1 = dup2(BQ[oc0 + 1]);
            #pragma unroll
            for (int k = 0; k < 6; k++) { q0[k] = b0; q1[k] = b1; }
            #pragma unroll 4
            for (int ic = 0; ic < 32; ic++) {
                const float* fr = F + ic * 108 + col;
                ulonglong2 V0 = *(const ulonglong2*)(fr);
                ulonglong2 V1 = *(const ulonglong2*)(fr + 4);
                ulonglong2 V2 = *(const ulonglong2*)(fr + 8);
                u64 wp = *(const u64*)(WQ + ic * 16 + 2 * ocg);
                float w0f, w1f; unpack2(wp, w0f, w1f);
                u64 w0 = dup2(w0f), w1 = dup2(w1f);
                q0[0] = ffma2(w0, V0.x, q0[0]);
                q0[1] = ffma2(w0, V0.y, q0[1]);
                q0[2] = ffma2(w0, V1.x, q0[2]);
                q0[3] = ffma2(w0, V1.y, q0[3]);
                q0[4] = ffma2(w0, V2.x, q0[4]);
                q0[5] = ffma2(w0, V2.y, q0[5]);
                q1[0] = ffma2(w1, V0.x, q1[0]);
                q1[1] = ffma2(w1, V0.y, q1[1]);
                q1[2] = ffma2(w1, V1.x, q1[2]);
                q1[3] = ffma2(w1, V1.y, q1[3]);
                q1[4] = ffma2(w1, V2.x, q1[4]);
                q1[5] = ffma2(w1, V2.y, q1[5]);
            }
            ulonglong2* qd0 = (ulonglong2*)(Q + oc0 * 108 + col);
            ulonglong2* qd1 = (ulonglong2*)(Q + (oc0 + 1) * 108 + col);
            ulonglong2 s;
            s.x = q0[0]; s.y = q0[1]; qd0[0] = s;
            s.x = q0[2]; s.y = q0[3]; qd0[1] = s;
            s.x = q0[4]; s.y = q0[5]; qd0[2] = s;
            s.x = q1[0]; s.y = q1[1]; qd1[0] = s;
            s.x = q1[2]; s.y = q1[3]; qd1[1] = s;
            s.x = q1[4]; s.y = q1[5]; qd1[2] = s;
        }
        __syncthreads();
        if (tid == 0) {
            float t = RED[0] + RED[1] + RED[2] + RED[3] + bcfc;
            float conf = 1.f / (1.f + expf(-t));
            s_flag = (conf < 0.9f) ? 1 : 0;
        }
        __syncthreads();
        if (!s_flag) break;

        // ===== Phase 2: a = tanh(conv48->32) on [Q;F]; F += a =====
        // 16 oc-pairs x 9 row-tiles = 144 threads
        float t0[12], t1[12];
        int oc0 = 0, col = 0;
        const bool act = tid < 144;
        if (act) {
            int ocp = tid & 15, rt = tid >> 4;
            oc0 = ocp << 1; col = rt * 12;
            u64 s0[6], s1[6];
            u64 b0 = dup2(BA[oc0]), b1 = dup2(BA[oc0 + 1]);
            #pragma unroll
            for (int k = 0; k < 6; k++) { s0[k] = b0; s1[k] = b1; }
            #pragma unroll 4
            for (int ic = 0; ic < 16; ic++) {
                const float* qr = Q + ic * 108 + col;
                ulonglong2 V0 = *(const ulonglong2*)(qr);
                ulonglong2 V1 = *(const ulonglong2*)(qr + 4);
                ulonglong2 V2 = *(const ulonglong2*)(qr + 8);
                u64 wp = *(const u64*)(WA + ic * 32 + oc0);
                float w0f, w1f; unpack2(wp, w0f, w1f);
                u64 w0 = dup2(w0f), w1 = dup2(w1f);
                s0[0] = ffma2(w0, V0.x, s0[0]);
                s0[1] = ffma2(w0, V0.y, s0[1]);
                s0[2] = ffma2(w0, V1.x, s0[2]);
                s0[3] = ffma2(w0, V1.y, s0[3]);
                s0[4] = ffma2(w0, V2.x, s0[4]);
                s0[5] = ffma2(w0, V2.y, s0[5]);
                s1[0] = ffma2(w1, V0.x, s1[0]);
                s1[1] = ffma2(w1, V0.y, s1[1]);
                s1[2] = ffma2(w1, V1.x, s1[2]);
                s1[3] = ffma2(w1, V1.y, s1[3]);
                s1[4] = ffma2(w1, V2.x, s1[4]);
                s1[5] = ffma2(w1, V2.y, s1[5]);
            }
            #pragma unroll 4
            for (int ic = 0; ic < 32; ic++) {
                const float* fr = F + ic * 108 + col;
                ulonglong2 V0 = *(const ulonglong2*)(fr);
                ulonglong2 V1 = *(const ulonglong2*)(fr + 4);
                ulonglong2 V2 = *(const ulonglong2*)(fr + 8);
                u64 wp = *(const u64*)(WA + (16 + ic) * 32 + oc0);
                float w0f, w1f; unpack2(wp, w0f, w1f);
                u64 w0 = dup2(w0f), w1 = dup2(w1f);
                s0[0] = ffma2(w0, V0.x, s0[0]);
                s0[1] = ffma2(w0, V0.y, s0[1]);
                s0[2] = ffma2(w0, V1.x, s0[2]);
                s0[3] = ffma2(w0, V1.y, s0[3]);
                s0[4] = ffma2(w0, V2.x, s0[4]);
                s0[5] = ffma2(w0, V2.y, s0[5]);
                s1[0] = ffma2(w1, V0.x, s1[0]);
                s1[1] = ffma2(w1, V0.y, s1[1]);
                s1[2] = ffma2(w1, V1.x, s1[2]);
                s1[3] = ffma2(w1, V1.y, s1[3]);
                s1[4] = ffma2(w1, V2.x, s1[4]);
                s1[5] = ffma2(w1, V2.y, s1[5]);
            }
            #pragma unroll
            for (int k = 0; k < 6; k++) {
                float xa, xb2;
                unpack2(s0[k], xa, xb2);
                t0[2 * k] = fast_tanh(xa); t0[2 * k + 1] = fast_tanh(xb2);
                unpack2(s1[k], xa, xb2);
                t1[2 * k] = fast_tanh(xa); t1[2 * k + 1] = fast_tanh(xb2);
            }
        }
        __syncthreads();   // all reads of old F before any write
        if (act) {
            float4* fd0 = (float4*)(F + oc0 * 108 + col);
            float4* fd1 = (float4*)(F + (oc0 + 1) * 108 + col);
            #pragma unroll
            for (int k = 0; k < 3; k++) {
                float4 v = fd0[k];
                v.x += t0[4 * k]; v.y += t0[4 * k + 1];
                v.z += t0[4 * k + 2]; v.w += t0[4 * k + 3];
                fd0[k] = v;
                float4 w = fd1[k];
                w.x += t1[4 * k]; w.y += t1[4 * k + 1];
                w.z += t1[4 * k + 2]; w.w += t1[4 * k + 3];
                fd1[k] = w;
            }
        }
        __syncthreads();
    }

    // ===== Final classifier =====
    float acc[10];
    #pragma unroll
    for (int k = 0; k < 10; k++) acc[k] = 0.f;
    for (int j = tid; j < 2592; j += 256) {
        int ic = j / 81, px = j % 81;
        float fv = F[ic * 108 + (px / 9) * 12 + (px % 9)];
        #pragma unroll
        for (int k = 0; k < 10; k++) acc[k] += fv * w_cls[k * 2592 + j];
    }
    #pragma unroll
    for (int k = 0; k < 10; k++) {
        float v = acc[k];
        #pragma unroll
        for (int o = 16; o > 0; o >>= 1)
            v += __shfl_down_sync(0xffffffffu, v, o);
        if (lane == 0) RED[k * 8 + wid] = v;
    }
    __syncthreads();
    if (tid < 10) {
        float t = b_cls[tid];
        #pragma unroll
        for (int w = 0; w < 8; w++) t += RED[tid * 8 + w];
        out[(size_t)b * 10 + tid] = t;
    }
}

// ---------------------------------------------------------------------------
extern "C" void kernel_launch(void* const* d_in, const int* in_sizes, int n_in,
                              void* d_out, int out_size)
{
    const float* x     = (const float*)d_in[0];
    const float* w_b1  = (const float*)d_in[1];
    const float* b_b1  = (const float*)d_in[2];
    const float* w_b2  = (const float*)d_in[3];
    const float* b_b2  = (const float*)d_in[4];
    const float* w_b3  = (const float*)d_in[5];
    const float* b_b3  = (const float*)d_in[6];
    const float* w_cf  = (const float*)d_in[7];
    const float* b_cf  = (const float*)d_in[8];
    const float* w_cfc = (const float*)d_in[9];
    const float* b_cfc = (const float*)d_in[10];
    const float* w_q   = (const float*)d_in[11];
    const float* b_q   = (const float*)d_in[12];
    const float* w_a   = (const float*)d_in[13];
    const float* b_a   = (const float*)d_in[14];
    const float* w_cls = (const float*)d_in[15];
    const float* b_cls = (const float*)d_in[16];

    int B = in_sizes[0] / 3072;
    if (B > 8192) B = 8192;

    float* g_f = nullptr;
    cudaGetSymbolAddress((void**)&g_f, g_f_scratch);

    base_kernel<<<B, 256>>>(x, w_b1, b_b1, w_b2, b_b2, w_b3, b_b3, g_f);
    loop_kernel<<<B, 256>>>(g_f, w_cf, b_cf, w_cfc, b_cfc,
                            w_q, b_q, w_a, b_a, w_cls, b_cls,
                            (float*)d_out);
}